// round 5
// baseline (speedup 1.0000x reference)
#include <cuda_runtime.h>
#include <cuda_bf16.h>
#include <math.h>
#include <stdint.h>

// ---------------------------------------------------------------------------
// Problem constants
// ---------------------------------------------------------------------------
#define N_ROWS    4096
#define DIM       512
#define VOCAB     128000
#define NCOLTILES 500       // VOCAB / 256
#define NROWTILES 32        // N_ROWS / 128
#define NCHUNKS   8         // DIM / 64
#define NPSUM     (4 * NCOLTILES)   // per-warpN(64-col) partials = 2000

// smem tiles (SW128, 128 B/row): A = 128x64 bf16 (16KB), B = 256x64 bf16 (32KB)
#define A_BYTES     16384
#define B_BYTES     32768
#define STAGE_BYTES (2 * A_BYTES + 2 * B_BYTES)   // Ahi|Alo|Bhi|Blo = 96KB
#define SMEM_DYN    (2 * STAGE_BYTES + 1024)      // 193KB

// ---------------------------------------------------------------------------
// Device scratch (allocation-free: __device__ globals)
// ---------------------------------------------------------------------------
__device__ unsigned short g_Ehi[(size_t)N_ROWS * DIM];
__device__ unsigned short g_Elo[(size_t)N_ROWS * DIM];
__device__ unsigned short g_Whi[(size_t)VOCAB * DIM];
__device__ unsigned short g_Wlo[(size_t)VOCAB * DIM];
__device__ float g_psum[(size_t)N_ROWS * NPSUM];
__device__ float g_rowloss[N_ROWS];

// ---------------------------------------------------------------------------
// PTX helpers
// ---------------------------------------------------------------------------
__device__ __forceinline__ uint32_t smem_u32(const void* p) {
    uint32_t a;
    asm("{ .reg .u64 t; cvta.to.shared.u64 t, %1; cvt.u32.u64 %0, t; }" : "=r"(a) : "l"(p));
    return a;
}
#define SWZ128(off) ((off) ^ (((off) >> 3) & 0x70))

__device__ __forceinline__ void cp16(uint32_t dst, const void* src) {
    asm volatile("cp.async.cg.shared.global [%0], [%1], 16;" :: "r"(dst), "l"(src));
}
#define CP_COMMIT() asm volatile("cp.async.commit_group;" ::: "memory")
#define CP_WAIT(n)  asm volatile("cp.async.wait_group %0;" :: "n"(n) : "memory")

__device__ __forceinline__ void ldmx4(uint32_t* r, uint32_t a) {
    asm volatile("ldmatrix.sync.aligned.m8n8.x4.shared.b16 {%0,%1,%2,%3}, [%4];"
                 : "=r"(r[0]), "=r"(r[1]), "=r"(r[2]), "=r"(r[3]) : "r"(a));
}
__device__ __forceinline__ void mma16816(float* d, const uint32_t* a,
                                         uint32_t b0, uint32_t b1) {
    asm volatile(
        "mma.sync.aligned.m16n8k16.row.col.f32.bf16.bf16.f32 "
        "{%0,%1,%2,%3}, {%4,%5,%6,%7}, {%8,%9}, {%0,%1,%2,%3};"
        : "+f"(d[0]), "+f"(d[1]), "+f"(d[2]), "+f"(d[3])
        : "r"(a[0]), "r"(a[1]), "r"(a[2]), "r"(a[3]), "r"(b0), "r"(b1));
}

// ---------------------------------------------------------------------------
// Split kernels: f32 -> (bf16 hi, bf16 lo = bf16(x - hi))
// ---------------------------------------------------------------------------
__device__ __forceinline__ void split4(const float4 v, unsigned short* h, unsigned short* l) {
    float xs[4] = {v.x, v.y, v.z, v.w};
    #pragma unroll
    for (int j = 0; j < 4; j++) {
        __nv_bfloat16 hb = __float2bfloat16(xs[j]);
        float r = xs[j] - __bfloat162float(hb);
        __nv_bfloat16 lb = __float2bfloat16(r);
        h[j] = *reinterpret_cast<unsigned short*>(&hb);
        l[j] = *reinterpret_cast<unsigned short*>(&lb);
    }
}
__global__ __launch_bounds__(256) void split_E_kernel(const float* __restrict__ src) {
    size_t i = (size_t)blockIdx.x * 256 + threadIdx.x;
    if (i * 4 >= (size_t)N_ROWS * DIM) return;
    unsigned short h[4], l[4];
    split4(((const float4*)src)[i], h, l);
    ((uint2*)g_Ehi)[i] = make_uint2((uint32_t)h[0] | ((uint32_t)h[1] << 16),
                                    (uint32_t)h[2] | ((uint32_t)h[3] << 16));
    ((uint2*)g_Elo)[i] = make_uint2((uint32_t)l[0] | ((uint32_t)l[1] << 16),
                                    (uint32_t)l[2] | ((uint32_t)l[3] << 16));
}
__global__ __launch_bounds__(256) void split_W_kernel(const float* __restrict__ src) {
    size_t i = (size_t)blockIdx.x * 256 + threadIdx.x;
    if (i * 4 >= (size_t)VOCAB * DIM) return;
    unsigned short h[4], l[4];
    split4(((const float4*)src)[i], h, l);
    ((uint2*)g_Whi)[i] = make_uint2((uint32_t)h[0] | ((uint32_t)h[1] << 16),
                                    (uint32_t)h[2] | ((uint32_t)h[3] << 16));
    ((uint2*)g_Wlo)[i] = make_uint2((uint32_t)l[0] | ((uint32_t)l[1] << 16),
                                    (uint32_t)l[2] | ((uint32_t)l[3] << 16));
}

// ---------------------------------------------------------------------------
// cp.async stage loader: Ahi|Alo (128x64) + Bhi|Blo (256x64), SW128 swizzled
// ---------------------------------------------------------------------------
__device__ __forceinline__ void load_stage(uint32_t buf_u32, int stage, int k0,
                                           int blockM, int blockN, int tid) {
    uint32_t base = buf_u32 + stage * STAGE_BYTES;
    // A: 128 rows, 2 arrays
    #pragma unroll
    for (int i = 0; i < 4; i++) {
        int q = tid + i * 256;          // 0..1023
        int row = q >> 3;
        int c16 = q & 7;
        uint32_t sw = SWZ128((uint32_t)(row * 128 + c16 * 16));
        size_t eoff = (size_t)(blockM + row) * DIM + k0 + c16 * 8;
        cp16(base + sw, &g_Ehi[eoff]);
        cp16(base + A_BYTES + sw, &g_Elo[eoff]);
    }
    // B: 256 rows, 2 arrays
    uint32_t bbase = base + 2 * A_BYTES;
    #pragma unroll
    for (int i = 0; i < 8; i++) {
        int q = tid + i * 256;          // 0..2047
        int row = q >> 3;
        int c16 = q & 7;
        uint32_t sw = SWZ128((uint32_t)(row * 128 + c16 * 16));
        size_t woff = (size_t)(blockN + row) * DIM + k0 + c16 * 8;
        cp16(bbase + sw, &g_Whi[woff]);
        cp16(bbase + B_BYTES + sw, &g_Wlo[woff]);
    }
    CP_COMMIT();
}

// ---------------------------------------------------------------------------
// Main HMMA GEMM + fused CE-partials kernel. CTA = 128x256 tile.
// Warps: 2x4 (M x N); warp tile 64x64; 3-term bf16 split, fp32 acc.
// ---------------------------------------------------------------------------
__global__ __launch_bounds__(256, 1) void gemm_mma_kernel(
    const float* __restrict__ bias,
    float* __restrict__ logits)
{
    extern __shared__ char dynsmem[];
    __shared__ float s_bias[256];

    const int tid  = threadIdx.x;
    const int wid  = tid >> 5;
    const int lid  = tid & 31;
    const int warpM = wid & 1;         // 0..1  -> 64 rows each
    const int warpN = wid >> 1;        // 0..3  -> 64 cols each
    const int blockM = blockIdx.x * 128;
    const int blockN = blockIdx.y * 256;

    uint32_t raw = smem_u32(dynsmem);
    uint32_t buf_u32 = (raw + 1023) & ~1023u;

    s_bias[tid] = bias[blockN + tid];

    float d[4][8][4];
    #pragma unroll
    for (int mt = 0; mt < 4; mt++)
        #pragma unroll
        for (int n = 0; n < 8; n++)
            #pragma unroll
            for (int c = 0; c < 4; c++) d[mt][n][c] = 0.0f;

    const int lid15 = lid & 15;
    const int khalf = (lid >> 4) * 16;       // 0 or 16 bytes (k0-7 / k8-15)
    const int rowA  = warpM * 64 + lid15;
    const int rowB  = warpN * 64 + lid15;

    load_stage(buf_u32, 0, 0, blockM, blockN, tid);

    #pragma unroll
    for (int i = 0; i < NCHUNKS; i++) {
        if (i < NCHUNKS - 1) {
            load_stage(buf_u32, (i + 1) & 1, (i + 1) * 64, blockM, blockN, tid);
            CP_WAIT(1);
        } else {
            CP_WAIT(0);
        }
        __syncthreads();

        const uint32_t sb = buf_u32 + (i & 1) * STAGE_BYTES;
        const uint32_t sbB = sb + 2 * A_BYTES;
        #pragma unroll
        for (int ks = 0; ks < 4; ks++) {
            const uint32_t kb = (uint32_t)(ks * 32 + khalf);
            // B fragments for the whole warp n64: 8 ldsm.x4
            uint32_t bh[4][4], bl[4][4];
            #pragma unroll
            for (int ng = 0; ng < 4; ng++) {
                uint32_t off = SWZ128((uint32_t)((rowB + ng * 16) * 128) + kb);
                ldmx4(bh[ng], sbB + off);
                ldmx4(bl[ng], sbB + B_BYTES + off);
            }
            // A per mt, reuse B regs across mt
            #pragma unroll
            for (int mt = 0; mt < 4; mt++) {
                uint32_t off = SWZ128((uint32_t)((rowA + mt * 16) * 128) + kb);
                uint32_t ah[4], al[4];
                ldmx4(ah, sb + off);
                ldmx4(al, sb + A_BYTES + off);
                #pragma unroll
                for (int ng = 0; ng < 4; ng++) {
                    mma16816(d[mt][ng * 2 + 0], ah, bh[ng][0], bh[ng][2]);
                    mma16816(d[mt][ng * 2 + 1], ah, bh[ng][1], bh[ng][3]);
                    mma16816(d[mt][ng * 2 + 0], ah, bl[ng][0], bl[ng][2]);
                    mma16816(d[mt][ng * 2 + 1], ah, bl[ng][1], bl[ng][3]);
                    mma16816(d[mt][ng * 2 + 0], al, bh[ng][0], bh[ng][2]);
                    mma16816(d[mt][ng * 2 + 1], al, bh[ng][1], bh[ng][3]);
                }
            }
        }
        __syncthreads();
    }

    // ---------------- epilogue: bias + exp-sum + logit stores ----------------
    const int g   = lid >> 2;    // row within m16 tile
    const int tig = lid & 3;     // col pair selector

    float rsum[4][2];
    #pragma unroll
    for (int mt = 0; mt < 4; mt++) { rsum[mt][0] = 0.0f; rsum[mt][1] = 0.0f; }

    #pragma unroll
    for (int mt = 0; mt < 4; mt++) {
        const int row0 = blockM + warpM * 64 + mt * 16 + g;
        #pragma unroll
        for (int n = 0; n < 8; n++) {
            const int coll = warpN * 64 + (n >> 1) * 16 + (n & 1) * 8 + tig * 2;
            const float b0 = s_bias[coll], b1 = s_bias[coll + 1];
            float v0 = d[mt][n][0] + b0;
            float v1 = d[mt][n][1] + b1;
            float v2 = d[mt][n][2] + b0;
            float v3 = d[mt][n][3] + b1;
            rsum[mt][0] += __expf(v0) + __expf(v1);
            rsum[mt][1] += __expf(v2) + __expf(v3);
            size_t o0 = (size_t)row0 * VOCAB + blockN + coll;
            size_t o1 = (size_t)(row0 + 8) * VOCAB + blockN + coll;
            logits[o0]     = v0;
            logits[o0 + 1] = v1;
            logits[o1]     = v2;
            logits[o1 + 1] = v3;
        }
    }

    // reduce exp-sums over the quad (4 lanes share the same rows)
    #pragma unroll
    for (int mt = 0; mt < 4; mt++)
        #pragma unroll
        for (int h = 0; h < 2; h++) {
            float s = rsum[mt][h];
            s += __shfl_xor_sync(0xFFFFFFFF, s, 1);
            s += __shfl_xor_sync(0xFFFFFFFF, s, 2);
            rsum[mt][h] = s;
        }
    if (tig == 0) {
        const int pc = blockIdx.y * 4 + warpN;
        #pragma unroll
        for (int mt = 0; mt < 4; mt++) {
            int r0 = blockM + warpM * 64 + mt * 16 + g;
            g_psum[(size_t)r0 * NPSUM + pc]       = rsum[mt][0];
            g_psum[(size_t)(r0 + 8) * NPSUM + pc] = rsum[mt][1];
        }
    }
}

// ---------------------------------------------------------------------------
// Row reduce: logz = log(sum partials); loss_row = logz - logit[target]
// ---------------------------------------------------------------------------
__global__ __launch_bounds__(256) void row_reduce_kernel(
    const float* __restrict__ logits,
    const int*   __restrict__ tgt32)
{
    __shared__ float sm[256];
    const int row = blockIdx.x;
    const int tid = threadIdx.x;
    float acc = 0.0f;
    for (int i = tid; i < NPSUM; i += 256)
        acc += g_psum[(size_t)row * NPSUM + i];
    sm[tid] = acc;
    __syncthreads();
    for (int s = 128; s > 0; s >>= 1) {
        if (tid < s) sm[tid] += sm[tid + s];
        __syncthreads();
    }
    if (tid == 0) {
        float logz = logf(sm[0]);
        bool is64 = ((tgt32[1] | tgt32[3] | tgt32[5] | tgt32[7]) == 0);
        int tgt = is64 ? tgt32[2 * row] : tgt32[row];
        g_rowloss[row] = logz - logits[(size_t)row * VOCAB + tgt];
    }
}

__global__ __launch_bounds__(256) void finalize_kernel(float* __restrict__ out) {
    __shared__ float sm[256];
    const int tid = threadIdx.x;
    float v = 0.0f;
    for (int i = tid; i < N_ROWS; i += 256) v += g_rowloss[i];
    sm[tid] = v;
    __syncthreads();
    for (int s = 128; s > 0; s >>= 1) {
        if (tid < s) sm[tid] += sm[tid + s];
        __syncthreads();
    }
    if (tid == 0) out[0] = sm[0] / (float)N_ROWS;
}

// ---------------------------------------------------------------------------
extern "C" void kernel_launch(void* const* d_in, const int* in_sizes, int n_in,
                              void* d_out, int out_size)
{
    const float* E   = (const float*)d_in[0];
    const int*   tgt = (const int*)d_in[1];
    const float* W   = (const float*)d_in[2];
    const float* b   = (const float*)d_in[3];
    float* out = (float*)d_out;

    const long long nv = (long long)N_ROWS * VOCAB;
    const int loss_off = ((long long)out_size == nv + 1) ? 1 : 0;
    float* logits = out + loss_off;

    cudaFuncSetAttribute(gemm_mma_kernel,
                         cudaFuncAttributeMaxDynamicSharedMemorySize, SMEM_DYN);

    split_E_kernel<<<(N_ROWS * DIM / 4 + 255) / 256, 256>>>(E);
    split_W_kernel<<<((size_t)VOCAB * DIM / 4 + 255) / 256, 256>>>(W);

    dim3 grid(NROWTILES, NCOLTILES);
    gemm_mma_kernel<<<grid, 256, SMEM_DYN>>>(b, logits);

    row_reduce_kernel<<<N_ROWS, 256>>>(logits, tgt);
    if (loss_off == 1) finalize_kernel<<<1, 256>>>(out);
}

// round 6
// speedup vs baseline: 1.1493x; 1.1493x over previous
#include <cuda_runtime.h>
#include <cuda_bf16.h>
#include <math.h>
#include <stdint.h>

// ---------------------------------------------------------------------------
// Problem constants
// ---------------------------------------------------------------------------
#define N_ROWS    4096
#define DIM       512
#define VOCAB     128000
#define NCOLTILES 1000      // VOCAB / 128
#define NROWTILES 32        // N_ROWS / 128
#define KCHUNK    32
#define NCHUNKS   16        // DIM / 32
#define NPSUM     (2 * NCOLTILES)

// smem tile: 128 rows x 32 bf16 = 64 B/row, SW64 swizzle -> 8 KB per array
#define TILE_BYTES  8192
#define STAGE_BYTES 32768   // Ahi | Alo | Bhi | Blo
#define SMEM_DYN    (2 * STAGE_BYTES + 1024)   // 66.5 KB -> 2 CTAs/SM

// ---------------------------------------------------------------------------
// Device scratch (allocation-free: __device__ globals)
// ---------------------------------------------------------------------------
__device__ unsigned short g_Ehi[(size_t)N_ROWS * DIM];
__device__ unsigned short g_Elo[(size_t)N_ROWS * DIM];
__device__ unsigned short g_Whi[(size_t)VOCAB * DIM];
__device__ unsigned short g_Wlo[(size_t)VOCAB * DIM];
__device__ float g_psum[(size_t)N_ROWS * NPSUM];
__device__ float g_rowloss[N_ROWS];

// ---------------------------------------------------------------------------
// PTX helpers
// ---------------------------------------------------------------------------
__device__ __forceinline__ uint32_t smem_u32(const void* p) {
    uint32_t a;
    asm("{ .reg .u64 t; cvta.to.shared.u64 t, %1; cvt.u32.u64 %0, t; }" : "=r"(a) : "l"(p));
    return a;
}
// SW64: 64-byte rows, atom = 8 rows; XOR bits [4:5] with row bits [1:2]
#define SWZ64(off) ((off) ^ (((off) >> 3) & 0x30))

__device__ __forceinline__ void cp16(uint32_t dst, const void* src) {
    asm volatile("cp.async.cg.shared.global [%0], [%1], 16;" :: "r"(dst), "l"(src));
}
#define CP_COMMIT() asm volatile("cp.async.commit_group;" ::: "memory")
#define CP_WAIT(n)  asm volatile("cp.async.wait_group %0;" :: "n"(n) : "memory")

__device__ __forceinline__ void ldmx4(uint32_t* r, uint32_t a) {
    asm volatile("ldmatrix.sync.aligned.m8n8.x4.shared.b16 {%0,%1,%2,%3}, [%4];"
                 : "=r"(r[0]), "=r"(r[1]), "=r"(r[2]), "=r"(r[3]) : "r"(a));
}
__device__ __forceinline__ void mma16816(float* d, const uint32_t* a,
                                         uint32_t b0, uint32_t b1) {
    asm volatile(
        "mma.sync.aligned.m16n8k16.row.col.f32.bf16.bf16.f32 "
        "{%0,%1,%2,%3}, {%4,%5,%6,%7}, {%8,%9}, {%0,%1,%2,%3};"
        : "+f"(d[0]), "+f"(d[1]), "+f"(d[2]), "+f"(d[3])
        : "r"(a[0]), "r"(a[1]), "r"(a[2]), "r"(a[3]), "r"(b0), "r"(b1));
}

// ---------------------------------------------------------------------------
// Fused split kernel: f32 -> (bf16 hi, bf16 lo = bf16(x - hi)) for E and W
// ---------------------------------------------------------------------------
#define E_F4 ((size_t)N_ROWS * DIM / 4)          // 524288
#define W_F4 ((size_t)VOCAB * DIM / 4)           // 16384000

__global__ __launch_bounds__(256) void split_all_kernel(
    const float* __restrict__ E, const float* __restrict__ W)
{
    size_t i = (size_t)blockIdx.x * 256 + threadIdx.x;
    const float4* src;
    unsigned short *dh, *dl;
    size_t j;
    if (i < E_F4) {
        src = (const float4*)E; dh = g_Ehi; dl = g_Elo; j = i;
    } else {
        j = i - E_F4;
        if (j >= W_F4) return;
        src = (const float4*)W; dh = g_Whi; dl = g_Wlo;
    }
    float4 v = src[j];
    float xs[4] = {v.x, v.y, v.z, v.w};
    unsigned short h[4], l[4];
    #pragma unroll
    for (int c = 0; c < 4; c++) {
        __nv_bfloat16 hb = __float2bfloat16(xs[c]);
        float r = xs[c] - __bfloat162float(hb);
        __nv_bfloat16 lb = __float2bfloat16(r);
        h[c] = *reinterpret_cast<unsigned short*>(&hb);
        l[c] = *reinterpret_cast<unsigned short*>(&lb);
    }
    ((uint2*)dh)[j] = make_uint2((uint32_t)h[0] | ((uint32_t)h[1] << 16),
                                 (uint32_t)h[2] | ((uint32_t)h[3] << 16));
    ((uint2*)dl)[j] = make_uint2((uint32_t)l[0] | ((uint32_t)l[1] << 16),
                                 (uint32_t)l[2] | ((uint32_t)l[3] << 16));
}

// ---------------------------------------------------------------------------
// cp.async stage loader: Ahi|Alo|Bhi|Blo, 128x32 bf16 each, SW64 swizzled
// ---------------------------------------------------------------------------
__device__ __forceinline__ void load_stage(uint32_t buf_u32, int stage, int k0,
                                           int blockM, int blockN, int tid) {
    uint32_t base = buf_u32 + stage * STAGE_BYTES;
    #pragma unroll
    for (int i = 0; i < 2; i++) {
        int q = tid + i * 256;          // 0..511
        int row = q >> 2;
        int c16 = q & 3;
        uint32_t sw = SWZ64((uint32_t)(row * 64 + c16 * 16));
        size_t eoff = (size_t)(blockM + row) * DIM + k0 + c16 * 8;
        size_t woff = (size_t)(blockN + row) * DIM + k0 + c16 * 8;
        cp16(base + 0 * TILE_BYTES + sw, &g_Ehi[eoff]);
        cp16(base + 1 * TILE_BYTES + sw, &g_Elo[eoff]);
        cp16(base + 2 * TILE_BYTES + sw, &g_Whi[woff]);
        cp16(base + 3 * TILE_BYTES + sw, &g_Wlo[woff]);
    }
    CP_COMMIT();
}

// ---------------------------------------------------------------------------
// Main HMMA GEMM + fused CE-partials. CTA = 128x128, warps 4x2, warp 32x64.
// 2 CTAs/SM for latency hiding.
// ---------------------------------------------------------------------------
__global__ __launch_bounds__(256, 2) void gemm_mma_kernel(
    const float* __restrict__ bias,
    float* __restrict__ logits)
{
    extern __shared__ char dynsmem[];
    __shared__ float s_bias[128];

    const int tid  = threadIdx.x;
    const int wid  = tid >> 5;
    const int lid  = tid & 31;
    const int warpM = wid & 3;         // 0..3 -> 32 rows
    const int warpN = wid >> 2;        // 0..1 -> 64 cols
    const int blockM = blockIdx.x * 128;
    const int blockN = blockIdx.y * 128;

    uint32_t raw = smem_u32(dynsmem);
    uint32_t buf_u32 = (raw + 1023) & ~1023u;

    if (tid < 128) s_bias[tid] = bias[blockN + tid];

    float d[2][8][4];
    #pragma unroll
    for (int mt = 0; mt < 2; mt++)
        #pragma unroll
        for (int n = 0; n < 8; n++)
            #pragma unroll
            for (int c = 0; c < 4; c++) d[mt][n][c] = 0.0f;

    const int lid15 = lid & 15;
    const int khalf = (lid >> 4) * 16;       // byte offset: k0-7 vs k8-15
    const int rowA  = warpM * 32 + lid15;
    const int rowB  = warpN * 64 + lid15;

    load_stage(buf_u32, 0, 0, blockM, blockN, tid);

    #pragma unroll 1
    for (int i = 0; i < NCHUNKS; i++) {
        if (i < NCHUNKS - 1) {
            load_stage(buf_u32, (i + 1) & 1, (i + 1) * KCHUNK, blockM, blockN, tid);
            CP_WAIT(1);
        } else {
            CP_WAIT(0);
        }
        __syncthreads();

        const uint32_t sb = buf_u32 + (i & 1) * STAGE_BYTES;
        #pragma unroll
        for (int ks = 0; ks < 2; ks++) {
            const uint32_t kb = (uint32_t)(ks * 32 + khalf);
            uint32_t ah[2][4], al[2][4];
            #pragma unroll
            for (int mt = 0; mt < 2; mt++) {
                uint32_t off = SWZ64((uint32_t)((rowA + mt * 16) * 64) + kb);
                ldmx4(ah[mt], sb + off);
                ldmx4(al[mt], sb + TILE_BYTES + off);
            }
            #pragma unroll
            for (int ng = 0; ng < 4; ng++) {
                uint32_t off = SWZ64((uint32_t)((rowB + ng * 16) * 64) + kb);
                uint32_t bh[4], bl[4];
                ldmx4(bh, sb + 2 * TILE_BYTES + off);
                ldmx4(bl, sb + 3 * TILE_BYTES + off);
                #pragma unroll
                for (int mt = 0; mt < 2; mt++) {
                    mma16816(d[mt][ng * 2 + 0], ah[mt], bh[0], bh[2]);
                    mma16816(d[mt][ng * 2 + 1], ah[mt], bh[1], bh[3]);
                    mma16816(d[mt][ng * 2 + 0], ah[mt], bl[0], bl[2]);
                    mma16816(d[mt][ng * 2 + 1], ah[mt], bl[1], bl[3]);
                    mma16816(d[mt][ng * 2 + 0], al[mt], bh[0], bh[2]);
                    mma16816(d[mt][ng * 2 + 1], al[mt], bh[1], bh[3]);
                }
            }
        }
        __syncthreads();
    }

    // ---------------- epilogue: bias + exp-sum + logit stores ----------------
    const int g   = lid >> 2;
    const int tig = lid & 3;

    float rsum[2][2] = {{0.0f, 0.0f}, {0.0f, 0.0f}};

    #pragma unroll
    for (int mt = 0; mt < 2; mt++) {
        const int row0 = blockM + warpM * 32 + mt * 16 + g;
        #pragma unroll
        for (int n = 0; n < 8; n++) {
            const int coll = warpN * 64 + (n >> 1) * 16 + (n & 1) * 8 + tig * 2;
            const float b0 = s_bias[coll], b1 = s_bias[coll + 1];
            float v0 = d[mt][n][0] + b0;
            float v1 = d[mt][n][1] + b1;
            float v2 = d[mt][n][2] + b0;
            float v3 = d[mt][n][3] + b1;
            rsum[mt][0] += __expf(v0) + __expf(v1);
            rsum[mt][1] += __expf(v2) + __expf(v3);
            size_t o0 = (size_t)row0 * VOCAB + blockN + coll;
            size_t o1 = (size_t)(row0 + 8) * VOCAB + blockN + coll;
            logits[o0]     = v0;
            logits[o0 + 1] = v1;
            logits[o1]     = v2;
            logits[o1 + 1] = v3;
        }
    }

    #pragma unroll
    for (int mt = 0; mt < 2; mt++)
        #pragma unroll
        for (int h = 0; h < 2; h++) {
            float s = rsum[mt][h];
            s += __shfl_xor_sync(0xFFFFFFFF, s, 1);
            s += __shfl_xor_sync(0xFFFFFFFF, s, 2);
            rsum[mt][h] = s;
        }
    if (tig == 0) {
        const int pc = blockIdx.y * 2 + warpN;
        #pragma unroll
        for (int mt = 0; mt < 2; mt++) {
            int r0 = blockM + warpM * 32 + mt * 16 + g;
            g_psum[(size_t)r0 * NPSUM + pc]       = rsum[mt][0];
            g_psum[(size_t)(r0 + 8) * NPSUM + pc] = rsum[mt][1];
        }
    }
}

// ---------------------------------------------------------------------------
// Row reduce + finalize
// ---------------------------------------------------------------------------
__global__ __launch_bounds__(256) void row_reduce_kernel(
    const float* __restrict__ logits,
    const int*   __restrict__ tgt32)
{
    __shared__ float sm[256];
    const int row = blockIdx.x;
    const int tid = threadIdx.x;
    float acc = 0.0f;
    for (int i = tid; i < NPSUM; i += 256)
        acc += g_psum[(size_t)row * NPSUM + i];
    sm[tid] = acc;
    __syncthreads();
    for (int s = 128; s > 0; s >>= 1) {
        if (tid < s) sm[tid] += sm[tid + s];
        __syncthreads();
    }
    if (tid == 0) {
        float logz = logf(sm[0]);
        bool is64 = ((tgt32[1] | tgt32[3] | tgt32[5] | tgt32[7]) == 0);
        int tgt = is64 ? tgt32[2 * row] : tgt32[row];
        g_rowloss[row] = logz - logits[(size_t)row * VOCAB + tgt];
    }
}

__global__ __launch_bounds__(256) void finalize_kernel(float* __restrict__ out) {
    __shared__ float sm[256];
    const int tid = threadIdx.x;
    float v = 0.0f;
    for (int i = tid; i < N_ROWS; i += 256) v += g_rowloss[i];
    sm[tid] = v;
    __syncthreads();
    for (int s = 128; s > 0; s >>= 1) {
        if (tid < s) sm[tid] += sm[tid + s];
        __syncthreads();
    }
    if (tid == 0) out[0] = sm[0] / (float)N_ROWS;
}

// ---------------------------------------------------------------------------
extern "C" void kernel_launch(void* const* d_in, const int* in_sizes, int n_in,
                              void* d_out, int out_size)
{
    const float* E   = (const float*)d_in[0];
    const int*   tgt = (const int*)d_in[1];
    const float* W   = (const float*)d_in[2];
    const float* b   = (const float*)d_in[3];
    float* out = (float*)d_out;

    const long long nv = (long long)N_ROWS * VOCAB;
    const int loss_off = ((long long)out_size == nv + 1) ? 1 : 0;
    float* logits = out + loss_off;

    cudaFuncSetAttribute(gemm_mma_kernel,
                         cudaFuncAttributeMaxDynamicSharedMemorySize, SMEM_DYN);

    size_t total_f4 = E_F4 + W_F4;
    split_all_kernel<<<(unsigned)((total_f4 + 255) / 256), 256>>>(E, W);

    dim3 grid(NROWTILES, NCOLTILES);
    gemm_mma_kernel<<<grid, 256, SMEM_DYN>>>(b, logits);

    row_reduce_kernel<<<N_ROWS, 256>>>(logits, tgt);
    if (loss_off == 1) finalize_kernel<<<1, 256>>>(out);
}

// round 7
// speedup vs baseline: 1.2301x; 1.0703x over previous
#include <cuda_runtime.h>
#include <cuda_bf16.h>
#include <math.h>
#include <stdint.h>

// ---------------------------------------------------------------------------
// Problem constants
// ---------------------------------------------------------------------------
#define N_ROWS    4096
#define DIM       512
#define VOCAB     128000
#define NCOLTILES 1000      // VOCAB / 128
#define NROWTILES 32        // N_ROWS / 128
#define KCHUNK    32
#define NCHUNKS   16        // DIM / 32
#define NPSUM     (2 * NCOLTILES)
#define NSTAGES   3

// smem tile: 128 rows x 32 bf16 = 64 B/row, SW64 swizzle -> 8 KB per array
#define TILE_BYTES  8192
#define STAGE_BYTES 32768   // Ahi | Alo | Bhi | Blo
#define SMEM_DYN    (NSTAGES * STAGE_BYTES + 1024)   // ~97.3 KB -> 2 CTAs/SM

// ---------------------------------------------------------------------------
// Device scratch (allocation-free: __device__ globals)
// ---------------------------------------------------------------------------
__device__ unsigned short g_Ehi[(size_t)N_ROWS * DIM];
__device__ unsigned short g_Elo[(size_t)N_ROWS * DIM];
__device__ unsigned short g_Whi[(size_t)VOCAB * DIM];
__device__ unsigned short g_Wlo[(size_t)VOCAB * DIM];
__device__ float g_psum[(size_t)N_ROWS * NPSUM];
__device__ float g_rowloss[N_ROWS];

// ---------------------------------------------------------------------------
// PTX helpers
// ---------------------------------------------------------------------------
__device__ __forceinline__ uint32_t smem_u32(const void* p) {
    uint32_t a;
    asm("{ .reg .u64 t; cvta.to.shared.u64 t, %1; cvt.u32.u64 %0, t; }" : "=r"(a) : "l"(p));
    return a;
}
// SW64: 64-byte rows, atom = 8 rows; XOR bits [4:5] with row bits [1:2]
#define SWZ64(off) ((off) ^ (((off) >> 3) & 0x30))

__device__ __forceinline__ void cp16(uint32_t dst, const void* src) {
    asm volatile("cp.async.cg.shared.global [%0], [%1], 16;" :: "r"(dst), "l"(src));
}
#define CP_COMMIT() asm volatile("cp.async.commit_group;" ::: "memory")
#define CP_WAIT(n)  asm volatile("cp.async.wait_group %0;" :: "n"(n) : "memory")

__device__ __forceinline__ void ldmx4(uint32_t* r, uint32_t a) {
    asm volatile("ldmatrix.sync.aligned.m8n8.x4.shared.b16 {%0,%1,%2,%3}, [%4];"
                 : "=r"(r[0]), "=r"(r[1]), "=r"(r[2]), "=r"(r[3]) : "r"(a));
}
__device__ __forceinline__ void mma16816(float* d, const uint32_t* a,
                                         uint32_t b0, uint32_t b1) {
    asm volatile(
        "mma.sync.aligned.m16n8k16.row.col.f32.bf16.bf16.f32 "
        "{%0,%1,%2,%3}, {%4,%5,%6,%7}, {%8,%9}, {%0,%1,%2,%3};"
        : "+f"(d[0]), "+f"(d[1]), "+f"(d[2]), "+f"(d[3])
        : "r"(a[0]), "r"(a[1]), "r"(a[2]), "r"(a[3]), "r"(b0), "r"(b1));
}

// ---------------------------------------------------------------------------
// Fused split kernel: f32 -> (bf16 hi, bf16 lo = bf16(x - hi)) for E and W
// ---------------------------------------------------------------------------
#define E_F4 ((size_t)N_ROWS * DIM / 4)          // 524288
#define W_F4 ((size_t)VOCAB * DIM / 4)           // 16384000

__global__ __launch_bounds__(256) void split_all_kernel(
    const float* __restrict__ E, const float* __restrict__ W)
{
    size_t i = (size_t)blockIdx.x * 256 + threadIdx.x;
    const float4* src;
    unsigned short *dh, *dl;
    size_t j;
    if (i < E_F4) {
        src = (const float4*)E; dh = g_Ehi; dl = g_Elo; j = i;
    } else {
        j = i - E_F4;
        if (j >= W_F4) return;
        src = (const float4*)W; dh = g_Whi; dl = g_Wlo;
    }
    float4 v = src[j];
    float xs[4] = {v.x, v.y, v.z, v.w};
    unsigned short h[4], l[4];
    #pragma unroll
    for (int c = 0; c < 4; c++) {
        __nv_bfloat16 hb = __float2bfloat16(xs[c]);
        float r = xs[c] - __bfloat162float(hb);
        __nv_bfloat16 lb = __float2bfloat16(r);
        h[c] = *reinterpret_cast<unsigned short*>(&hb);
        l[c] = *reinterpret_cast<unsigned short*>(&lb);
    }
    ((uint2*)dh)[j] = make_uint2((uint32_t)h[0] | ((uint32_t)h[1] << 16),
                                 (uint32_t)h[2] | ((uint32_t)h[3] << 16));
    ((uint2*)dl)[j] = make_uint2((uint32_t)l[0] | ((uint32_t)l[1] << 16),
                                 (uint32_t)l[2] | ((uint32_t)l[3] << 16));
}

// ---------------------------------------------------------------------------
// cp.async stage loader: Ahi|Alo|Bhi|Blo, 128x32 bf16 each, SW64 swizzled
// ---------------------------------------------------------------------------
__device__ __forceinline__ void load_stage(uint32_t buf_u32, int stage, int k0,
                                           int blockM, int blockN, int tid) {
    uint32_t base = buf_u32 + stage * STAGE_BYTES;
    #pragma unroll
    for (int i = 0; i < 2; i++) {
        int q = tid + i * 256;          // 0..511
        int row = q >> 2;
        int c16 = q & 3;
        uint32_t sw = SWZ64((uint32_t)(row * 64 + c16 * 16));
        size_t eoff = (size_t)(blockM + row) * DIM + k0 + c16 * 8;
        size_t woff = (size_t)(blockN + row) * DIM + k0 + c16 * 8;
        cp16(base + 0 * TILE_BYTES + sw, &g_Ehi[eoff]);
        cp16(base + 1 * TILE_BYTES + sw, &g_Elo[eoff]);
        cp16(base + 2 * TILE_BYTES + sw, &g_Whi[woff]);
        cp16(base + 3 * TILE_BYTES + sw, &g_Wlo[woff]);
    }
    CP_COMMIT();
}

// ---------------------------------------------------------------------------
// Main HMMA GEMM + fused CE-partials. CTA = 128x128, warps 4x2, warp 32x64.
// 3-stage cp.async pipeline, ONE __syncthreads per chunk, 2 CTAs/SM.
// ---------------------------------------------------------------------------
__global__ __launch_bounds__(256, 2) void gemm_mma_kernel(
    const float* __restrict__ bias,
    float* __restrict__ logits)
{
    extern __shared__ char dynsmem[];
    __shared__ float s_bias[128];

    const int tid  = threadIdx.x;
    const int wid  = tid >> 5;
    const int lid  = tid & 31;
    const int warpM = wid & 3;         // 0..3 -> 32 rows
    const int warpN = wid >> 2;        // 0..1 -> 64 cols
    const int blockM = blockIdx.x * 128;
    const int blockN = blockIdx.y * 128;

    uint32_t raw = smem_u32(dynsmem);
    uint32_t buf_u32 = (raw + 1023) & ~1023u;

    if (tid < 128) s_bias[tid] = bias[blockN + tid];

    float d[2][8][4];
    #pragma unroll
    for (int mt = 0; mt < 2; mt++)
        #pragma unroll
        for (int n = 0; n < 8; n++)
            #pragma unroll
            for (int c = 0; c < 4; c++) d[mt][n][c] = 0.0f;

    const int lid15 = lid & 15;
    const int khalf = (lid >> 4) * 16;       // byte offset: k0-7 vs k8-15
    const int rowA  = warpM * 32 + lid15;
    const int rowB  = warpN * 64 + lid15;

    // prologue: fill stages 0 and 1
    load_stage(buf_u32, 0, 0, blockM, blockN, tid);
    load_stage(buf_u32, 1, KCHUNK, blockM, blockN, tid);

    #pragma unroll
    for (int i = 0; i < NCHUNKS; i++) {
        if (i < NCHUNKS - 1) CP_WAIT(1); else CP_WAIT(0);
        __syncthreads();

        // issue the load for stage i+2 BEFORE computing stage i (overlap)
        if (i + 2 < NCHUNKS)
            load_stage(buf_u32, (i + 2) % NSTAGES, (i + 2) * KCHUNK,
                       blockM, blockN, tid);

        const uint32_t sb = buf_u32 + (i % NSTAGES) * STAGE_BYTES;
        #pragma unroll
        for (int ks = 0; ks < 2; ks++) {
            const uint32_t kb = (uint32_t)(ks * 32 + khalf);
            uint32_t ah[2][4], al[2][4];
            #pragma unroll
            for (int mt = 0; mt < 2; mt++) {
                uint32_t off = SWZ64((uint32_t)((rowA + mt * 16) * 64) + kb);
                ldmx4(ah[mt], sb + off);
                ldmx4(al[mt], sb + TILE_BYTES + off);
            }
            #pragma unroll
            for (int ng = 0; ng < 4; ng++) {
                uint32_t off = SWZ64((uint32_t)((rowB + ng * 16) * 64) + kb);
                uint32_t bh[4], bl[4];
                ldmx4(bh, sb + 2 * TILE_BYTES + off);
                ldmx4(bl, sb + 3 * TILE_BYTES + off);
                #pragma unroll
                for (int mt = 0; mt < 2; mt++) {
                    mma16816(d[mt][ng * 2 + 0], ah[mt], bh[0], bh[2]);
                    mma16816(d[mt][ng * 2 + 1], ah[mt], bh[1], bh[3]);
                    mma16816(d[mt][ng * 2 + 0], ah[mt], bl[0], bl[2]);
                    mma16816(d[mt][ng * 2 + 1], ah[mt], bl[1], bl[3]);
                    mma16816(d[mt][ng * 2 + 0], al[mt], bh[0], bh[2]);
                    mma16816(d[mt][ng * 2 + 1], al[mt], bh[1], bh[3]);
                }
            }
        }
    }

    // ---------------- epilogue: bias + exp-sum + logit stores ----------------
    const int g   = lid >> 2;
    const int tig = lid & 3;

    float rsum[2][2] = {{0.0f, 0.0f}, {0.0f, 0.0f}};

    #pragma unroll
    for (int mt = 0; mt < 2; mt++) {
        const int row0 = blockM + warpM * 32 + mt * 16 + g;
        #pragma unroll
        for (int n = 0; n < 8; n++) {
            const int coll = warpN * 64 + (n >> 1) * 16 + (n & 1) * 8 + tig * 2;
            const float b0 = s_bias[coll], b1 = s_bias[coll + 1];
            float v0 = d[mt][n][0] + b0;
            float v1 = d[mt][n][1] + b1;
            float v2 = d[mt][n][2] + b0;
            float v3 = d[mt][n][3] + b1;
            rsum[mt][0] += __expf(v0) + __expf(v1);
            rsum[mt][1] += __expf(v2) + __expf(v3);
            size_t o0 = (size_t)row0 * VOCAB + blockN + coll;
            size_t o1 = (size_t)(row0 + 8) * VOCAB + blockN + coll;
            logits[o0]     = v0;
            logits[o0 + 1] = v1;
            logits[o1]     = v2;
            logits[o1 + 1] = v3;
        }
    }

    #pragma unroll
    for (int mt = 0; mt < 2; mt++)
        #pragma unroll
        for (int h = 0; h < 2; h++) {
            float s = rsum[mt][h];
            s += __shfl_xor_sync(0xFFFFFFFF, s, 1);
            s += __shfl_xor_sync(0xFFFFFFFF, s, 2);
            rsum[mt][h] = s;
        }
    if (tig == 0) {
        const int pc = blockIdx.y * 2 + warpN;
        #pragma unroll
        for (int mt = 0; mt < 2; mt++) {
            int r0 = blockM + warpM * 32 + mt * 16 + g;
            g_psum[(size_t)r0 * NPSUM + pc]       = rsum[mt][0];
            g_psum[(size_t)(r0 + 8) * NPSUM + pc] = rsum[mt][1];
        }
    }
}

// ---------------------------------------------------------------------------
// Row reduce + finalize
// ---------------------------------------------------------------------------
__global__ __launch_bounds__(256) void row_reduce_kernel(
    const float* __restrict__ logits,
    const int*   __restrict__ tgt32)
{
    __shared__ float sm[256];
    const int row = blockIdx.x;
    const int tid = threadIdx.x;
    float acc = 0.0f;
    for (int i = tid; i < NPSUM; i += 256)
        acc += g_psum[(size_t)row * NPSUM + i];
    sm[tid] = acc;
    __syncthreads();
    for (int s = 128; s > 0; s >>= 1) {
        if (tid < s) sm[tid] += sm[tid + s];
        __syncthreads();
    }
    if (tid == 0) {
        float logz = logf(sm[0]);
        bool is64 = ((tgt32[1] | tgt32[3] | tgt32[5] | tgt32[7]) == 0);
        int tgt = is64 ? tgt32[2 * row] : tgt32[row];
        g_rowloss[row] = logz - logits[(size_t)row * VOCAB + tgt];
    }
}

__global__ __launch_bounds__(256) void finalize_kernel(float* __restrict__ out) {
    __shared__ float sm[256];
    const int tid = threadIdx.x;
    float v = 0.0f;
    for (int i = tid; i < N_ROWS; i += 256) v += g_rowloss[i];
    sm[tid] = v;
    __syncthreads();
    for (int s = 128; s > 0; s >>= 1) {
        if (tid < s) sm[tid] += sm[tid + s];
        __syncthreads();
    }
    if (tid == 0) out[0] = sm[0] / (float)N_ROWS;
}

// ---------------------------------------------------------------------------
extern "C" void kernel_launch(void* const* d_in, const int* in_sizes, int n_in,
                              void* d_out, int out_size)
{
    const float* E   = (const float*)d_in[0];
    const int*   tgt = (const int*)d_in[1];
    const float* W   = (const float*)d_in[2];
    const float* b   = (const float*)d_in[3];
    float* out = (float*)d_out;

    const long long nv = (long long)N_ROWS * VOCAB;
    const int loss_off = ((long long)out_size == nv + 1) ? 1 : 0;
    float* logits = out + loss_off;

    cudaFuncSetAttribute(gemm_mma_kernel,
                         cudaFuncAttributeMaxDynamicSharedMemorySize, SMEM_DYN);

    size_t total_f4 = E_F4 + W_F4;
    split_all_kernel<<<(unsigned)((total_f4 + 255) / 256), 256>>>(E, W);

    dim3 grid(NROWTILES, NCOLTILES);
    gemm_mma_kernel<<<grid, 256, SMEM_DYN>>>(b, logits);

    row_reduce_kernel<<<N_ROWS, 256>>>(logits, tgt);
    if (loss_off == 1) finalize_kernel<<<1, 256>>>(out);
}